// round 7
// baseline (speedup 1.0000x reference)
#include <cuda_runtime.h>
#include <math.h>
#include <stdint.h>

typedef unsigned long long ull;

#define T_STEPS 512
#define NHID    512
#define NCH     1024
#define BATCH   64
#define HB      32768
#define NCTA    128
#define NTHR    512

// smem layout in ull units
#define W_ULL    18432            // 9 gemms * 256 kpairs * 8 cols
#define SROW     34               // state row stride (32 slots + pad, 272B, 16B-aligned)
#define PRED_ULL (64*SROW)        // 2176
#define BUF_ULL  (2*PRED_ULL)     // 4352 (2 predecessors per buffer)
#define SB_ULL   (2*BUF_ULL)      // 8704 (double buffer)
#define SMEM_BYTES ((W_ULL + SB_ULL) * 8)   // 217088

__device__ float g_X[(size_t)T_STEPS * BATCH * NCH];   // x @ W0[:512]
__device__ float g_S[9][HB];
__device__ ull   g_WT2[(size_t)9 * 256 * 1024];        // [g][kpair][j] = (w[2p][j], w[2p+1][j])
__device__ unsigned int g_bar_arrive;
__device__ unsigned int g_bar_gen;

__device__ __forceinline__ void fma2(ull &d, ull a, ull b) {
    asm("fma.rn.f32x2 %0, %1, %2, %0;" : "+l"(d) : "l"(a), "l"(b));
}
__device__ __forceinline__ ull dup2(float v) {
    ull r; asm("mov.b64 %0, {%1, %1};" : "=l"(r) : "f"(v)); return r;
}
__device__ __forceinline__ float2 unpk(ull v) {
    float2 f; asm("mov.b64 {%0, %1}, %2;" : "=f"(f.x), "=f"(f.y) : "l"(v)); return f;
}
__device__ __forceinline__ uint32_t smem_u32(const void* p) {
    uint32_t a;
    asm("{ .reg .u64 t; cvta.to.shared.u64 t, %1; cvt.u32.u64 %0, t; }" : "=r"(a) : "l"(p));
    return a;
}
__device__ __forceinline__ void cp16(uint32_t d, const void* s) {
    asm volatile("cp.async.cg.shared.global [%0], [%1], 16;" :: "r"(d), "l"(s) : "memory");
}

__device__ __forceinline__ void grid_bar() {
    __syncthreads();
    if (threadIdx.x == 0) {
        unsigned int gen = ((volatile unsigned int*)&g_bar_gen)[0];
        __threadfence();
        if (atomicAdd(&g_bar_arrive, 1u) == (unsigned)(NCTA - 1)) {
            g_bar_arrive = 0u;
            __threadfence();
            ((volatile unsigned int*)&g_bar_gen)[0] = gen + 1u;
        } else {
            while (((volatile unsigned int*)&g_bar_gen)[0] == gen) { }
        }
        __threadfence();
    }
    __syncthreads();
}

__device__ __forceinline__ float actf(int a, float x) {
    if (a == 0) return tanhf(x);
    if (a == 1) return fmaxf(x, 0.f);
    if (a == 2) return 1.f / (1.f + expf(-x));
    return x;
}

// ------- one-time weight transpose into k-pair-interleaved layout -------
__global__ void wtrans_kernel(const float* __restrict__ W0, const float* __restrict__ Ws) {
    int g = blockIdx.x;   // 0..8; 8 = W0 hidden half
    int p = blockIdx.y;   // 0..255 k-pairs
    const float* src = (g == 8) ? (W0 + (size_t)NHID * NCH) : (Ws + (size_t)g * NHID * NCH);
    const float* ra = src + (size_t)(2 * p) * NCH;
    const float* rb = ra + NCH;
    for (int j = threadIdx.x; j < NCH; j += 256) {
        ull v; asm("mov.b64 %0, {%1, %2};" : "=l"(v) : "f"(ra[j]), "f"(rb[j]));
        g_WT2[((size_t)g * 256 + p) * 1024 + j] = v;
    }
}

// ------- X = inputs @ W0[:512] precompute -------
__global__ void __launch_bounds__(256) xprep_kernel(const float* __restrict__ A,
                                                    const float* __restrict__ W) {
    __shared__ ull   AsD[64][17];
    __shared__ float Bs[16][68];
    const int tid = threadIdx.x;
    const int n0 = blockIdx.x * 64;
    const int m0 = blockIdx.y * 64;
    const int tx = tid & 15;
    const int ty = tid >> 4;
    ull acc[4][2];
#pragma unroll
    for (int i = 0; i < 4; ++i) { acc[i][0] = 0ull; acc[i][1] = 0ull; }
    for (int k0 = 0; k0 < 512; k0 += 16) {
        {
            int am = tid >> 2, a4 = tid & 3;
            float4 v = *(const float4*)(A + (size_t)(m0 + am) * 512 + k0 + a4 * 4);
            AsD[am][a4 * 4 + 0] = dup2(v.x); AsD[am][a4 * 4 + 1] = dup2(v.y);
            AsD[am][a4 * 4 + 2] = dup2(v.z); AsD[am][a4 * 4 + 3] = dup2(v.w);
        }
        {
            int bk = tid >> 4, b4 = tid & 15;
            *(float4*)&Bs[bk][b4 * 4] = *(const float4*)(W + (size_t)(k0 + bk) * NCH + n0 + b4 * 4);
        }
        __syncthreads();
#pragma unroll
        for (int k = 0; k < 16; ++k) {
            ulonglong2 b = *(const ulonglong2*)&Bs[k][tx * 4];
#pragma unroll
            for (int i = 0; i < 4; ++i) {
                ull a = AsD[ty * 4 + i][k];
                fma2(acc[i][0], a, b.x);
                fma2(acc[i][1], a, b.y);
            }
        }
        __syncthreads();
    }
#pragma unroll
    for (int i = 0; i < 4; ++i) {
        float2 lo = unpk(acc[i][0]), hi = unpk(acc[i][1]);
        *(float4*)(g_X + (size_t)(m0 + ty * 4 + i) * NCH + n0 + tx * 4) =
            make_float4(lo.x, lo.y, hi.x, hi.y);
    }
}

// ------- one phase: NG gemms of a DAG level; weights resident in smem -------
// CTA owns 4 j-positions (c col j, h col j+512) for ALL 64 rows, full K=512.
// 512 threads: kq = tid>>8 splits K in half; (r,jj) = (tid>>2 & 63, tid & 3).
template<int NG, int NP, bool MEAN, bool BIAS>
__device__ __forceinline__ void phase(const ull* __restrict__ ws, ull* sb, uint32_t sb_u32,
    const float* p0g, const float* p1g,
    int gi0, int gi1, int gi2, int gi3,
    int a0, int a1, int a2, int a3,
    float* d0, float* d1, float* d2, float* d3,
    const float* bias, float* outp, int j0)
{
    const int tid = threadIdx.x;
    const int kq = tid >> 8;
    const int tl = tid & 255;
    const int r  = tl >> 2;
    const int jj = tl & 3;
    const float* preds[2] = { p0g, p1g };

    const ull* wg[NG];
#pragma unroll
    for (int g = 0; g < NG; ++g) {
        int gi = (g == 0) ? gi0 : (g == 1) ? gi1 : (g == 2) ? gi2 : gi3;
        wg[g] = ws + (size_t)gi * 2048;
    }

    ull acc[NG][2];
#pragma unroll
    for (int g = 0; g < NG; ++g) { acc[g][0] = 0ull; acc[g][1] = 0ull; }

    auto stage = [&](int c, int buf) {
#pragma unroll
        for (int it = 0; it < NP * 2; ++it) {
            int i = tid + it * NTHR;
            int p   = i >> 10;
            int rem = i & 1023;
            int rr  = rem >> 4;
            int seg = rem & 15;
            const float* src = preds[p] + (size_t)rr * NHID +
                (seg < 8 ? c * 32 + seg * 4 : 256 + c * 32 + (seg - 8) * 4);
            uint32_t dst = sb_u32 +
                (uint32_t)((buf * BUF_ULL + p * PRED_ULL + rr * SROW) * 8 + seg * 16);
            cp16(dst, src);
        }
        asm volatile("cp.async.commit_group;" ::: "memory");
    };

    stage(0, 0);
    for (int c = 0; c < 8; ++c) {
        if (c < 7) {
            stage(c + 1, (c + 1) & 1);
            asm volatile("cp.async.wait_group 1;" ::: "memory");
        } else {
            asm volatile("cp.async.wait_group 0;" ::: "memory");
        }
        __syncthreads();
        const ull* sp0 = sb + (c & 1) * BUF_ULL + r * SROW + kq * 16;
        const ull* sp1 = sp0 + PRED_ULL;
        const int kbase = (kq * 128 + c * 16) * 8;
#pragma unroll 4
        for (int q = 0; q < 16; ++q) {
            ull s0 = sp0[q];
            ull s1 = (NP == 2) ? sp1[q] : 0ull;
#pragma unroll
            for (int g = 0; g < NG; ++g) {
                const ull* wp = wg[g] + kbase + q * 8;
                const int pp = (NP == 1) ? 0 : ((NG == 4) ? (g >> 1) : g);
                ull sv = (pp == 0) ? s0 : s1;
                fma2(acc[g][0], sv, wp[jj]);
                fma2(acc[g][1], sv, wp[4 + jj]);
            }
        }
        __syncthreads();
    }

    // K-half reduction (state buffers are now free scratch)
    ull* red = sb;
    if (kq == 1) {
#pragma unroll
        for (int g = 0; g < NG; ++g) {
            red[(tl * NG + g) * 2 + 0] = acc[g][0];
            red[(tl * NG + g) * 2 + 1] = acc[g][1];
        }
    }
    __syncthreads();
    if (kq == 0) {
        const int col = j0 + jj;
        float macc = 0.f;
#pragma unroll
        for (int g = 0; g < NG; ++g) {
            float2 a  = unpk(acc[g][0]);
            float2 b  = unpk(red[(tl * NG + g) * 2 + 0]);
            float2 ah = unpk(acc[g][1]);
            float2 bh = unpk(red[(tl * NG + g) * 2 + 1]);
            float cs = a.x + a.y + b.x + b.y;
            float hs = ah.x + ah.y + bh.x + bh.y;
            if (BIAS) {
                cs += bias[(size_t)r * NCH + col];
                hs += bias[(size_t)r * NCH + NHID + col];
            }
            const int pp = (NP == 1) ? 0 : ((NG == 4) ? (g >> 1) : g);
            float sp = preds[pp][(size_t)r * NHID + col];
            int act = (g == 0) ? a0 : (g == 1) ? a1 : (g == 2) ? a2 : a3;
            float cg = 1.f / (1.f + expf(-cs));
            float hv = actf(act, hs);
            float nv = sp + cg * (hv - sp);
            float* dst = (g == 0) ? d0 : (g == 1) ? d1 : (g == 2) ? d2 : d3;
            if (dst) dst[(size_t)r * NHID + col] = nv;
            if (MEAN) macc += nv;
        }
        if (MEAN) {
#pragma unroll
            for (int st = 1; st <= 6; ++st)
                macc += g_S[st][(size_t)r * NHID + col];
            outp[(size_t)r * NHID + col] = macc * 0.125f;
        }
    }
}

__global__ void __launch_bounds__(NTHR, 1) recurrent_kernel(
    const float* __restrict__ hidden0, float* __restrict__ out, int write_tail)
{
    extern __shared__ ull smem[];
    ull* ws = smem;
    ull* sb = smem + W_ULL;
    uint32_t sb_u32 = smem_u32(sb);
    const int j0 = blockIdx.x * 4;

    // One-time: load this CTA's resident weight slice (all 9 gemms, 4 j-cols, full K)
    for (int i = threadIdx.x; i < W_ULL; i += NTHR) {
        int g    = i >> 11;
        int rem  = i & 2047;
        int kp   = rem >> 3;
        int slot = rem & 7;
        int half = slot >> 2;
        int jjj  = slot & 3;
        ws[i] = g_WT2[((size_t)g * 256 + kp) * 1024 + half * 512 + j0 + jjj];
    }
    __syncthreads();

    for (int t = 0; t < T_STEPS; ++t) {
        const float* hprev = (t == 0) ? hidden0 : (out + (size_t)(t - 1) * HB);
        // P0: s0 = hprev + sig(c)*(tanh(h)-hprev); weights gi=8 (W0 hidden half), bias = X[t]
        phase<1, 1, false, true>(ws, sb, sb_u32, hprev, nullptr, 8, 0, 0, 0, 0, 0, 0, 0,
            g_S[0], nullptr, nullptr, nullptr, g_X + (size_t)t * BATCH * NCH, nullptr, j0);
        grid_bar();
        // P1: s1(tanh), s2(relu) from s0
        phase<2, 1, false, false>(ws, sb, sb_u32, g_S[0], nullptr, 0, 1, 0, 0, 0, 1, 0, 0,
            g_S[1], g_S[2], nullptr, nullptr, nullptr, nullptr, j0);
        grid_bar();
        // P2: s3(sig,s1) s4(id,s1) s5(tanh,s2) s6(relu,s2)
        phase<4, 2, false, false>(ws, sb, sb_u32, g_S[1], g_S[2], 2, 3, 4, 5, 2, 3, 0, 1,
            g_S[3], g_S[4], g_S[5], g_S[6], nullptr, nullptr, j0);
        grid_bar();
        // P3: s7(sig,s3), s8(id,s4); fused mean(s1..s8) -> out[t]
        phase<2, 2, true, false>(ws, sb, sb_u32, g_S[3], g_S[4], 6, 7, 0, 0, 2, 3, 0, 0,
            nullptr, nullptr, nullptr, nullptr, nullptr, out + (size_t)t * HB, j0);
        grid_bar();
    }
    if (write_tail) {
        const float* src = out + (size_t)(T_STEPS - 1) * HB;
        float* dstp = out + (size_t)T_STEPS * HB;
        for (int i = blockIdx.x * NTHR + threadIdx.x; i < HB; i += NCTA * NTHR)
            dstp[i] = src[i];
    }
}

extern "C" void kernel_launch(void* const* d_in, const int* in_sizes, int n_in,
                              void* d_out, int out_size) {
    const float* inputs = (const float*)d_in[0];   // [512,64,512]
    const float* hidden = (const float*)d_in[1];   // [1,64,512]
    const float* W0     = (const float*)d_in[2];   // [1024,1024]
    const float* Ws     = (const float*)d_in[3];   // [8,512,1024]
    float* out = (float*)d_out;

    dim3 gw(9, 256);
    wtrans_kernel<<<gw, 256>>>(W0, Ws);

    dim3 gx(NCH / 64, (T_STEPS * BATCH) / 64);
    xprep_kernel<<<gx, 256>>>(inputs, W0);

    cudaFuncSetAttribute(recurrent_kernel,
                         cudaFuncAttributeMaxDynamicSharedMemorySize, SMEM_BYTES);
    int tail = (out_size >= T_STEPS * HB + HB) ? 1 : 0;
    recurrent_kernel<<<NCTA, NTHR, SMEM_BYTES>>>(hidden, out, tail);
}

// round 8
// speedup vs baseline: 1.4396x; 1.4396x over previous
#include <cuda_runtime.h>
#include <math.h>
#include <stdint.h>

typedef unsigned long long ull;

#define T_STEPS 512
#define NHID    512
#define NCH     1024
#define BATCH   64
#define HB      32768
#define NCTA    128
#define NTHR    512
#define NCHUNK  4

#define SA_STRIDE_F 520
#define SA_ULL   (32 * 260)            // 2 preds * 16 rows * 260 ull = 8320
#define WBUF_ULL (4 * 4 * 32 * 18)     // kq4 * (NGmax4 * 32 rows) * 18 = 9216
#define SMEM_BYTES ((SA_ULL + 2 * WBUF_ULL) * 8)   // 214016

__device__ float g_X[(size_t)T_STEPS * BATCH * NCH];   // x @ W0[:512]
__device__ float g_S[9][HB];
__device__ ull   g_WT2[(size_t)9 * 256 * 1024];        // [g][kpair][j] = (w[2p][j], w[2p+1][j])
__device__ unsigned int g_bar_arrive;
__device__ unsigned int g_bar_gen;

__device__ __forceinline__ void fma2(ull &d, ull a, ull b) {
    asm("fma.rn.f32x2 %0, %1, %2, %0;" : "+l"(d) : "l"(a), "l"(b));
}
__device__ __forceinline__ ull dup2(float v) {
    ull r; asm("mov.b64 %0, {%1, %1};" : "=l"(r) : "f"(v)); return r;
}
__device__ __forceinline__ float2 unpk(ull v) {
    float2 f; asm("mov.b64 {%0, %1}, %2;" : "=f"(f.x), "=f"(f.y) : "l"(v)); return f;
}
__device__ __forceinline__ uint32_t smem_u32(const void* p) {
    uint32_t a;
    asm("{ .reg .u64 t; cvta.to.shared.u64 t, %1; cvt.u32.u64 %0, t; }" : "=r"(a) : "l"(p));
    return a;
}
__device__ __forceinline__ void cp16(uint32_t d, const void* s) {
    asm volatile("cp.async.cg.shared.global [%0], [%1], 16;" :: "r"(d), "l"(s) : "memory");
}
__device__ __forceinline__ void cp_commit() {
    asm volatile("cp.async.commit_group;" ::: "memory");
}
__device__ __forceinline__ void cp_wait_all() {
    asm volatile("cp.async.wait_group 0;" ::: "memory");
}

__device__ __forceinline__ void grid_bar() {
    __syncthreads();
    if (threadIdx.x == 0) {
        unsigned int gen = ((volatile unsigned int*)&g_bar_gen)[0];
        __threadfence();
        if (atomicAdd(&g_bar_arrive, 1u) == (unsigned)(NCTA - 1)) {
            g_bar_arrive = 0u;
            __threadfence();
            ((volatile unsigned int*)&g_bar_gen)[0] = gen + 1u;
        } else {
            while (((volatile unsigned int*)&g_bar_gen)[0] == gen) { }
        }
        __threadfence();
    }
    __syncthreads();
}

__device__ __forceinline__ float actf(int a, float x) {
    if (a == 0) return tanhf(x);
    if (a == 1) return fmaxf(x, 0.f);
    if (a == 2) return 1.f / (1.f + expf(-x));
    return x;
}

// ================= prep kernel: weight transpose + X precompute (merged) =================
__global__ void __launch_bounds__(256) prep_kernel(const float* __restrict__ A,
                                                   const float* __restrict__ W0,
                                                   const float* __restrict__ Ws) {
    int bid = blockIdx.x;
    if (bid < 2304) {
        // ---- weight transpose: g = bid>>8, kpair p = bid&255 ----
        int g = bid >> 8, p = bid & 255;
        const float* src = (g == 8) ? (W0 + (size_t)NHID * NCH)
                                    : (Ws + (size_t)g * NHID * NCH);
        const float* ra = src + (size_t)(2 * p) * NCH;
        const float* rb = ra + NCH;
        for (int j = threadIdx.x; j < NCH; j += 256) {
            ull v; asm("mov.b64 %0, {%1, %2};" : "=l"(v) : "f"(ra[j]), "f"(rb[j]));
            g_WT2[((size_t)g * 256 + p) * 1024 + j] = v;
        }
        return;
    }
    // ---- X = inputs @ W0[:512] ----
    int idx = bid - 2304;
    __shared__ ull   AsD[64][17];
    __shared__ float Bs[16][68];
    const int tid = threadIdx.x;
    const int n0 = (idx & 15) * 64;
    const int m0 = (idx >> 4) * 64;
    const int tx = tid & 15;
    const int ty = tid >> 4;
    ull acc[4][2];
#pragma unroll
    for (int i = 0; i < 4; ++i) { acc[i][0] = 0ull; acc[i][1] = 0ull; }
    for (int k0 = 0; k0 < 512; k0 += 16) {
        {
            int am = tid >> 2, a4 = tid & 3;
            float4 v = *(const float4*)(A + (size_t)(m0 + am) * 512 + k0 + a4 * 4);
            AsD[am][a4 * 4 + 0] = dup2(v.x); AsD[am][a4 * 4 + 1] = dup2(v.y);
            AsD[am][a4 * 4 + 2] = dup2(v.z); AsD[am][a4 * 4 + 3] = dup2(v.w);
        }
        {
            int bk = tid >> 4, b4 = tid & 15;
            *(float4*)&Bs[bk][b4 * 4] = *(const float4*)(W0 + (size_t)(k0 + bk) * NCH + n0 + b4 * 4);
        }
        __syncthreads();
#pragma unroll
        for (int k = 0; k < 16; ++k) {
            ulonglong2 b = *(const ulonglong2*)&Bs[k][tx * 4];
#pragma unroll
            for (int i = 0; i < 4; ++i) {
                ull a = AsD[ty * 4 + i][k];
                fma2(acc[i][0], a, b.x);
                fma2(acc[i][1], a, b.y);
            }
        }
        __syncthreads();
    }
#pragma unroll
    for (int i = 0; i < 4; ++i) {
        float2 lo = unpk(acc[i][0]), hi = unpk(acc[i][1]);
        *(float4*)(g_X + (size_t)(m0 + ty * 4 + i) * NCH + n0 + tx * 4) =
            make_float4(lo.x, lo.y, hi.x, hi.y);
    }
}

// ================= one DAG level: NG fused gemms + gated update =================
// CTA tile: 16 rows (r0..r0+16) x 16 j-cols (j0..j0+16; c at j, h at j+512).
// Threads: jj=tid&15, rh=(tid>>4)&7 (2 rows each), kq=tid>>7 (4 K-quarters of 64 kpairs).
// Weights streamed L2->smem via cp.async, 4 chunks of 16 kpairs/kq, depth-1 overlap.
template<int NG, int NP, bool MEAN, bool BIAS>
__device__ __forceinline__ void phase(ull* smem, uint32_t smem_b,
    const float* p0g, const float* p1g,
    int gi0, int gi1, int gi2, int gi3,
    int a0, int a1, int a2, int a3,
    float* d0, float* d1, float* d2, float* d3,
    const float* bias, float* outp, int r0, int j0)
{
    ull* sa  = smem;
    ull* wsm = smem + SA_ULL;
    const uint32_t sa_u32 = smem_b;
    const uint32_t w_u32  = smem_b + SA_ULL * 8;
    const int tid = threadIdx.x;
    const int jj = tid & 15;
    const int rh = (tid >> 4) & 7;
    const int kq = tid >> 7;
    const int tl = tid & 127;                 // index within kq group
    const float* preds[2] = { p0g, p1g };
    const int gis[4] = { gi0, gi1, gi2, gi3 };

    // ---- stage states (cp.async) ----
#pragma unroll
    for (int it = 0; it < 4 * NP; ++it) {
        int i = tid + it * NTHR;              // < NP*2048
        int p = i >> 11, rem = i & 2047;
        int rr = rem >> 7, seg = rem & 127;
        const float* src = preds[p] + (size_t)(r0 + rr) * NHID + seg * 4;
        cp16(sa_u32 + (uint32_t)(((p * 16 + rr) * SA_STRIDE_F + seg * 4) * 4), src);
    }
    // ---- stage weight chunk 0 (same commit group) ----
    auto stage_w = [&](int c, int buf) {
        uint32_t dbase = w_u32 + (uint32_t)(buf * WBUF_ULL * 8);
#pragma unroll
        for (int it = 0; it < 2 * NG; ++it) {
            int i = tid + it * NTHR;          // < NG*1024
            int seg = i & 7;
            int row = i >> 3;                 // < 128*NG
            int q = row & 15, half = (row >> 4) & 1;
            int gk = row >> 5;
            int g = gk % NG, kqv = gk / NG;
            const ull* src = g_WT2 + ((size_t)gis[g] * 256 + kqv * 64 + c * 16 + q) * 1024
                             + j0 + half * 512 + seg * 2;
            cp16(dbase + (uint32_t)(row * 144 + seg * 16), src);
        }
    };
    stage_w(0, 0);
    cp_commit();

    ull acc[NG][2][2];
#pragma unroll
    for (int g = 0; g < NG; ++g)
#pragma unroll
        for (int rr = 0; rr < 2; ++rr) { acc[g][rr][0] = 0ull; acc[g][rr][1] = 0ull; }

    for (int c = 0; c < NCHUNK; ++c) {
        cp_wait_all();
        __syncthreads();
        if (c + 1 < NCHUNK) { stage_w(c + 1, (c + 1) & 1); cp_commit(); }
        const ull* wbase = wsm + (c & 1) * WBUF_ULL + (size_t)kq * NG * 576 + jj;
        const ull* s0 = sa + (rh * 2) * 260 + kq * 64 + c * 16;
        const ull* s1 = s0 + 16 * 260;
#pragma unroll
        for (int q = 0; q < 16; ++q) {
            ull s0a = s0[q], s0b = s0[260 + q];
            ull s1a = 0, s1b = 0;
            if (NP == 2) { s1a = s1[q]; s1b = s1[260 + q]; }
#pragma unroll
            for (int g = 0; g < NG; ++g) {
                const ull* wp = wbase + (g * 32 + q) * 18;
                ull wc = wp[0];
                ull wh = wp[288];
                const int pp = (NP == 1) ? 0 : ((NG == 4) ? (g >> 1) : g);
                ull va = (pp == 0) ? s0a : s1a;
                ull vb = (pp == 0) ? s0b : s1b;
                fma2(acc[g][0][0], va, wc);
                fma2(acc[g][1][0], vb, wc);
                fma2(acc[g][0][1], va, wh);
                fma2(acc[g][1][1], vb, wh);
            }
        }
    }

    // ---- epilogue: kq>0 write scalar partials into (dead) weight buf0; one sync ----
    float* redf = (float*)wsm;
    if (kq) {
#pragma unroll
        for (int g = 0; g < NG; ++g)
#pragma unroll
            for (int rr = 0; rr < 2; ++rr)
#pragma unroll
                for (int ch = 0; ch < 2; ++ch) {
                    float2 v = unpk(acc[g][rr][ch]);
                    redf[((g * 2 + rr) * 2 + ch) * 384 + (kq - 1) * 128 + tl] = v.x + v.y;
                }
    }
    __syncthreads();
    if (tid < 128) {
        const float* saf = (const float*)sa;
        const int col = j0 + jj;
        float macc[2] = { 0.f, 0.f };
#pragma unroll
        for (int g = 0; g < NG; ++g) {
            const int pp = (NP == 1) ? 0 : ((NG == 4) ? (g >> 1) : g);
            const int act = (g == 0) ? a0 : (g == 1) ? a1 : (g == 2) ? a2 : a3;
            float* dst = (g == 0) ? d0 : (g == 1) ? d1 : (g == 2) ? d2 : d3;
#pragma unroll
            for (int rr = 0; rr < 2; ++rr) {
                int row = rh * 2 + rr;
                float2 av = unpk(acc[g][rr][0]);
                float2 bv = unpk(acc[g][rr][1]);
                float cs = av.x + av.y, hs = bv.x + bv.y;
#pragma unroll
                for (int qv = 0; qv < 3; ++qv) {
                    cs += redf[((g * 2 + rr) * 2 + 0) * 384 + qv * 128 + tid];
                    hs += redf[((g * 2 + rr) * 2 + 1) * 384 + qv * 128 + tid];
                }
                if (BIAS) {
                    cs += bias[(size_t)(r0 + row) * NCH + col];
                    hs += bias[(size_t)(r0 + row) * NCH + 512 + col];
                }
                float sp = saf[(pp * 16 + row) * SA_STRIDE_F + col];
                float cg = 1.f / (1.f + expf(-cs));
                float hv = actf(act, hs);
                float nv = sp + cg * (hv - sp);
                if (dst) dst[(size_t)(r0 + row) * NHID + col] = nv;
                if (MEAN) macc[rr] += nv;
            }
        }
        if (MEAN) {
#pragma unroll
            for (int rr = 0; rr < 2; ++rr) {
                int row = rh * 2 + rr;
                float m = macc[rr];
#pragma unroll
                for (int st = 1; st <= 6; ++st)
                    m += g_S[st][(size_t)(r0 + row) * NHID + col];
                outp[(size_t)(r0 + row) * NHID + col] = m * 0.125f;
            }
        }
    }
}

__global__ void __launch_bounds__(NTHR, 1) recurrent_kernel(
    const float* __restrict__ hidden0, float* __restrict__ out, int write_tail)
{
    extern __shared__ ull smem[];
    uint32_t smem_b = smem_u32(smem);
    const int bid = blockIdx.x;
    const int r0 = (bid >> 5) * 16;
    const int j0 = (bid & 31) * 16;

    for (int t = 0; t < T_STEPS; ++t) {
        const float* hprev = (t == 0) ? hidden0 : (out + (size_t)(t - 1) * HB);
        // P0: s0 = hprev + sig(c)*(tanh(h)-hprev); gemm gi=8 (W0 hidden half), bias = X[t]
        phase<1, 1, false, true>(smem, smem_b, hprev, nullptr, 8, 0, 0, 0, 0, 0, 0, 0,
            g_S[0], nullptr, nullptr, nullptr, g_X + (size_t)t * BATCH * NCH, nullptr, r0, j0);
        grid_bar();
        // P1: s1(tanh), s2(relu) from s0
        phase<2, 1, false, false>(smem, smem_b, g_S[0], nullptr, 0, 1, 0, 0, 0, 1, 0, 0,
            g_S[1], g_S[2], nullptr, nullptr, nullptr, nullptr, r0, j0);
        grid_bar();
        // P2: s3(sig,s1) s4(id,s1) s5(tanh,s2) s6(relu,s2)
        phase<4, 2, false, false>(smem, smem_b, g_S[1], g_S[2], 2, 3, 4, 5, 2, 3, 0, 1,
            g_S[3], g_S[4], g_S[5], g_S[6], nullptr, nullptr, r0, j0);
        grid_bar();
        // P3: s7(sig,s3), s8(id,s4); fused mean(s1..s8) -> out[t]
        phase<2, 2, true, false>(smem, smem_b, g_S[3], g_S[4], 6, 7, 0, 0, 2, 3, 0, 0,
            nullptr, nullptr, nullptr, nullptr, nullptr, out + (size_t)t * HB, r0, j0);
        grid_bar();
    }
    if (write_tail) {
        const float* src = out + (size_t)(T_STEPS - 1) * HB;
        float* dstp = out + (size_t)T_STEPS * HB;
        for (int i = bid * NTHR + threadIdx.x; i < HB; i += NCTA * NTHR)
            dstp[i] = src[i];
    }
}

extern "C" void kernel_launch(void* const* d_in, const int* in_sizes, int n_in,
                              void* d_out, int out_size) {
    const float* inputs = (const float*)d_in[0];   // [512,64,512]
    const float* hidden = (const float*)d_in[1];   // [1,64,512]
    const float* W0     = (const float*)d_in[2];   // [1024,1024]
    const float* Ws     = (const float*)d_in[3];   // [8,512,1024]
    float* out = (float*)d_out;

    prep_kernel<<<2304 + 8192, 256>>>(inputs, W0, Ws);

    cudaFuncSetAttribute(recurrent_kernel,
                         cudaFuncAttributeMaxDynamicSharedMemorySize, SMEM_BYTES);
    int tail = (out_size >= T_STEPS * HB + HB) ? 1 : 0;
    recurrent_kernel<<<NCTA, NTHR, SMEM_BYTES>>>(hidden, out, tail);
}